// round 16
// baseline (speedup 1.0000x reference)
#include <cuda.h>
#include <cuda_runtime.h>
#include <cuda_bf16.h>
#include <math.h>

// Problem constants
#define Bz 4
#define Nn 4096
#define DM 1024
#define Hh 16
#define DEPTH 64
#define ROWS (Bz * Nn)          // 16384
#define BH (Bz * Hh)            // 64
#define NSEG 8
#define SEG_ROWS (Nn / NSEG)    // 512

// ---------------------------------------------------------------------------
// Scratch (device globals)
// ---------------------------------------------------------------------------
__device__ __align__(128) float g_Q[ROWS * DM];
__device__ __align__(128) float g_K[ROWS * DM];
__device__ __align__(128) float g_V[ROWS * DM];
__device__ __align__(128) float g_attn[ROWS * DM];
__device__ __align__(128) float g_proj[ROWS * DM];
__device__ __align__(128) float g_Wt[4 * DM * DM];
__device__ float g_KtQp[NSEG * BH * DEPTH * DEPTH];
__device__ float g_KtQ[BH * DEPTH * DEPTH];
__device__ float g_qsp[NSEG * BH * DEPTH];
__device__ float g_qs[BH * DEPTH];

__device__ __forceinline__ float tf32r(float x) {
    float r;
    asm("cvt.rna.tf32.f32 %0, %1;" : "=f"(r) : "f"(x));
    return r;
}
__device__ __forceinline__ unsigned smem_u32(const void* p) {
    unsigned a;
    asm("{ .reg .u64 t; cvta.to.shared.u64 t, %1; cvt.u32.u64 %0, t; }"
        : "=r"(a) : "l"(p));
    return a;
}

__device__ __forceinline__ void mma_tf32(float* d, const unsigned* a,
                                         unsigned b0, unsigned b1)
{
    asm volatile(
        "mma.sync.aligned.m16n8k8.row.col.f32.tf32.tf32.f32 "
        "{%0,%1,%2,%3}, {%4,%5,%6,%7}, {%8,%9}, {%0,%1,%2,%3};"
        : "+f"(d[0]), "+f"(d[1]), "+f"(d[2]), "+f"(d[3])
        : "r"(a[0]), "r"(a[1]), "r"(a[2]), "r"(a[3]), "r"(b0), "r"(b1));
}

#define LDMX4(r0, r1, r2, r3, addr) \
    asm volatile("ldmatrix.sync.aligned.m8n8.x4.shared.b16 {%0,%1,%2,%3}, [%4];" \
                 : "=r"(r0), "=r"(r1), "=r"(r2), "=r"(r3) : "r"(addr))

__device__ __forceinline__ void mbar_wait(unsigned mb, unsigned parity) {
    asm volatile(
        "{\n\t.reg .pred P;\n\t"
        "W_%=:\n\t"
        "mbarrier.try_wait.parity.acquire.cta.shared::cta.b64 P, [%0], %1, 0x989680;\n\t"
        "@P bra.uni D_%=;\n\t"
        "bra.uni W_%=;\n\t"
        "D_%=:\n\t}"
        :: "r"(mb), "r"(parity) : "memory");
}
__device__ __forceinline__ void mbar_arrive(unsigned mb) {
    asm volatile("mbarrier.arrive.shared.b64 _, [%0];" :: "r"(mb) : "memory");
}

// ---------------------------------------------------------------------------
// Weight transpose + tf32 rounding
// ---------------------------------------------------------------------------
__global__ void transpose_k(const float* __restrict__ W0, const float* __restrict__ W1,
                            const float* __restrict__ W2, const float* __restrict__ W3,
                            float* __restrict__ Wt)
{
    __shared__ float t[32][33];
    const int m = blockIdx.z;
    const float* W = (m == 0) ? W0 : (m == 1) ? W1 : (m == 2) ? W2 : W3;
    float* dst = Wt + (size_t)m * DM * DM;
    const int bx = blockIdx.x * 32;
    const int by = blockIdx.y * 32;
    const int tx = threadIdx.x, ty = threadIdx.y;
#pragma unroll
    for (int i = 0; i < 32; i += 8)
        t[ty + i][tx] = W[(size_t)(by + ty + i) * DM + bx + tx];
    __syncthreads();
#pragma unroll
    for (int i = 0; i < 32; i += 8)
        dst[(size_t)(bx + ty + i) * DM + by + tx] = tf32r(t[tx][ty + i]);
}

// ---------------------------------------------------------------------------
// tf32 mma.sync GEMM v11: CTA tile 256x128, 8 warps (4x2), warp tile 64x64,
// TMA SW128 KC=32, 3 stages, full/empty mbarriers, register fragment
// double-buffering, rotating producer. 256 threads, 1 CTA/SM.
// act: 0 none, 1 elu+1, 2 residual add.
// ---------------------------------------------------------------------------
#define KC 32
#define NCHUNK (DM / KC)            // 32
#define ASTG_A 32768                // 256 rows x 128B
#define ASTG_B 16384                // 128 rows x 128B
#define SM_MB 0
#define SM_A 1024
#define SM_B (SM_A + 3 * ASTG_A)    // 99328
#define SM_TOTAL (SM_B + 3 * ASTG_B)  // 148480

__device__ __forceinline__ void ld_group(unsigned aB, unsigned bB,
                                         const unsigned* rowA, const unsigned* rowB,
                                         unsigned sw, unsigned* fa, unsigned* fb)
{
#pragma unroll
    for (int mt = 0; mt < 4; ++mt)
        LDMX4(fa[4 * mt], fa[4 * mt + 1], fa[4 * mt + 2], fa[4 * mt + 3],
              aB + rowA[mt] + sw);
#pragma unroll
    for (int p = 0; p < 4; ++p)
        LDMX4(fb[4 * p], fb[4 * p + 1], fb[4 * p + 2], fb[4 * p + 3],
              bB + rowB[p] + sw);
}

__device__ __forceinline__ void gemm_body(
    const CUtensorMap* pA, const CUtensorMap* pB,
    const float* __restrict__ bias, float* __restrict__ C,
    int act, const float* __restrict__ resid)
{
    extern __shared__ char smem[];
    const unsigned sbase = smem_u32(smem);
    const int tid = threadIdx.x;
    const int wid = tid >> 5, lane = tid & 31;
    const int warpM = wid >> 1;     // 0..3 -> 64-row slab within 256
    const int warpN = wid & 1;      // 0..1 -> 64-col slab
    const int bm = blockIdx.y * 256;
    const int bn = blockIdx.x * 128;

    if (tid == 0) {
#pragma unroll
        for (int s = 0; s < 3; ++s) {
            asm volatile("mbarrier.init.shared.b64 [%0], 1;"
                         :: "r"(sbase + SM_MB + s * 8) : "memory");      // full
            asm volatile("mbarrier.init.shared.b64 [%0], 8;"
                         :: "r"(sbase + SM_MB + 24 + s * 8) : "memory"); // empty
        }
    }
    __syncthreads();

#define ISSUE_TMA(c)                                                              \
    do {                                                                          \
        const int _s = (c) % 3;                                                   \
        const unsigned _mb = sbase + SM_MB + _s * 8;                              \
        const int _k0 = (c) * KC;                                                 \
        asm volatile("mbarrier.arrive.expect_tx.shared.b64 _, [%0], 49152;"       \
                     :: "r"(_mb) : "memory");                                     \
        asm volatile("cp.async.bulk.tensor.2d.shared::cta.global.tile"            \
                     ".mbarrier::complete_tx::bytes [%0], [%1, {%2, %3}], [%4];"  \
                     :: "r"(sbase + SM_A + _s * ASTG_A), "l"(pA),                 \
                        "r"(_k0), "r"(bm), "r"(_mb) : "memory");                  \
        asm volatile("cp.async.bulk.tensor.2d.shared::cta.global.tile"            \
                     ".mbarrier::complete_tx::bytes [%0], [%1, {%2, %3}], [%4];"  \
                     :: "r"(sbase + SM_B + _s * ASTG_B), "l"(pB),                 \
                        "r"(_k0), "r"(bn), "r"(_mb) : "memory");                  \
    } while (0)

    if (tid == 0) { ISSUE_TMA(0); ISSUE_TMA(1); ISSUE_TMA(2); }

    // ldmatrix addressing (SW128 XOR = lr<<4)
    const int lt = lane >> 3, lr = lane & 7;
    const int ldrow = (lt & 1) * 8 + lr;
    unsigned segsw[4];
#pragma unroll
    for (int g = 0; g < 4; ++g)
        segsw[g] = (unsigned)((((lt >> 1) * 16 + g * 32)) ^ (lr << 4));
    unsigned rowA[4], rowB[4];
#pragma unroll
    for (int t4 = 0; t4 < 4; ++t4) {
        rowA[t4] = (warpM * 64 + t4 * 16 + ldrow) * 128;
        rowB[t4] = (warpN * 64 + t4 * 16 + ldrow) * 128;
    }

    float acc[4][8][4];
#pragma unroll
    for (int i = 0; i < 4; ++i)
#pragma unroll
        for (int j = 0; j < 8; ++j)
#pragma unroll
            for (int q = 0; q < 4; ++q) acc[i][j][q] = 0.0f;

    unsigned fA[2][16], fB[2][16];
    int cur = 0;

    // preload chunk 0, group 0
    mbar_wait(sbase + SM_MB + 0, 0);
    ld_group(sbase + SM_A, sbase + SM_B, rowA, rowB, segsw[0], fA[0], fB[0]);

    for (int c = 0; c < NCHUNK; ++c) {
        const int s = c % 3;
        const unsigned aB = sbase + SM_A + s * ASTG_A;
        const unsigned bB = sbase + SM_B + s * ASTG_B;
#pragma unroll
        for (int g = 0; g < 4; ++g) {
            const int nxt = cur ^ 1;
            if (g < 3) {
                ld_group(aB, bB, rowA, rowB, segsw[g + 1], fA[nxt], fB[nxt]);
            } else if (c + 1 < NCHUNK) {
                const int ns = (c + 1) % 3;
                mbar_wait(sbase + SM_MB + ns * 8, ((c + 1) / 3) & 1);
                ld_group(sbase + SM_A + ns * ASTG_A, sbase + SM_B + ns * ASTG_B,
                         rowA, rowB, segsw[0], fA[nxt], fB[nxt]);
            }
            const unsigned* af = fA[cur];
            const unsigned* bf = fB[cur];
#pragma unroll
            for (int mt = 0; mt < 4; ++mt)
#pragma unroll
                for (int p = 0; p < 4; ++p) {
                    mma_tf32(acc[mt][2 * p],     af + 4 * mt, bf[4 * p], bf[4 * p + 2]);
                    mma_tf32(acc[mt][2 * p + 1], af + 4 * mt, bf[4 * p + 1], bf[4 * p + 3]);
                }
            cur = nxt;
        }
        // all stage-c LDSMs complete (their consumer MMAs issued above)
        if (lane == 0) mbar_arrive(sbase + SM_MB + 24 + s * 8);
        // rotating producer: warp (c&7) refills stage s with chunk c+3
        if (c + 3 < NCHUNK && wid == (c & 7) && lane == 0) {
            mbar_wait(sbase + SM_MB + 24 + s * 8, (c / 3) & 1);
            ISSUE_TMA(c + 3);
        }
    }

    // epilogue (per-warp accumulators; no sync needed)
    const int gid = lane >> 2, tig = lane & 3;
#pragma unroll
    for (int mt = 0; mt < 4; ++mt) {
        const int r = bm + warpM * 64 + mt * 16 + gid;
#pragma unroll
        for (int nt = 0; nt < 8; ++nt) {
            const int cn = bn + warpN * 64 + nt * 8 + 2 * tig;
            const float b0 = bias[cn], b1 = bias[cn + 1];
            float v0 = acc[mt][nt][0] + b0;
            float v1 = acc[mt][nt][1] + b1;
            float v2 = acc[mt][nt][2] + b0;
            float v3 = acc[mt][nt][3] + b1;
            if (act == 1) {
                v0 = (v0 > 0.0f) ? (v0 + 1.0f) : __expf(v0);
                v1 = (v1 > 0.0f) ? (v1 + 1.0f) : __expf(v1);
                v2 = (v2 > 0.0f) ? (v2 + 1.0f) : __expf(v2);
                v3 = (v3 > 0.0f) ? (v3 + 1.0f) : __expf(v3);
            } else if (act == 2) {
                float2 r0 = *(const float2*)&resid[(size_t)r * DM + cn];
                float2 r1 = *(const float2*)&resid[(size_t)(r + 8) * DM + cn];
                v0 += r0.x; v1 += r0.y; v2 += r1.x; v3 += r1.y;
            }
            *(float2*)&C[(size_t)r * DM + cn] = make_float2(v0, v1);
            *(float2*)&C[(size_t)(r + 8) * DM + cn] = make_float2(v2, v3);
        }
    }
#undef ISSUE_TMA
}

__global__ __launch_bounds__(256, 1)
void gemm_qkv_k(const __grid_constant__ CUtensorMap tA0,
                const __grid_constant__ CUtensorMap tA1,
                const __grid_constant__ CUtensorMap tA2,
                const __grid_constant__ CUtensorMap tB0,
                const __grid_constant__ CUtensorMap tB1,
                const __grid_constant__ CUtensorMap tB2,
                const float* __restrict__ b0, const float* __restrict__ b1,
                const float* __restrict__ b2,
                float* __restrict__ C0, float* __restrict__ C1,
                float* __restrict__ C2)
{
    const int z = blockIdx.z;
    const CUtensorMap* pA = (z == 0) ? &tA0 : (z == 1) ? &tA1 : &tA2;
    const CUtensorMap* pB = (z == 0) ? &tB0 : (z == 1) ? &tB1 : &tB2;
    const float* bias = (z == 0) ? b0 : (z == 1) ? b1 : b2;
    float* C = (z == 0) ? C0 : (z == 1) ? C1 : C2;
    gemm_body(pA, pB, bias, C, (z < 2) ? 1 : 0, (const float*)0);
}

__global__ __launch_bounds__(256, 1)
void gemm_o_k(const __grid_constant__ CUtensorMap tA,
              const __grid_constant__ CUtensorMap tB,
              const float* __restrict__ bias, float* __restrict__ C,
              const float* __restrict__ resid)
{
    gemm_body(&tA, &tB, bias, C, 2, resid);
}

// ---------------------------------------------------------------------------
// ktq via mma
// ---------------------------------------------------------------------------
__global__ __launch_bounds__(128)
void ktq_k()
{
    __shared__ float Ks[2][16][68];
    __shared__ float Qs[2][16][68];

    const int bh = blockIdx.x;
    const int b = bh >> 4, h = bh & 15;
    const int seg = blockIdx.y;
    const int tid = threadIdx.x;
    const int wid = tid >> 5, lane = tid & 31;
    const int gid = lane >> 2, tig = lane & 3;
    const int lrow = tid >> 3;
    const int lcol = (tid & 7) * 8;

    float acc[8][4];
#pragma unroll
    for (int j = 0; j < 8; ++j)
#pragma unroll
        for (int q = 0; q < 4; ++q) acc[j][q] = 0.0f;
    float qsv = 0.0f;

    size_t gbase = ((size_t)(b * Nn + seg * SEG_ROWS + lrow)) * DM + h * DEPTH + lcol;
    float4 ka0 = *(const float4*)&g_K[gbase];
    float4 ka1 = *(const float4*)&g_K[gbase + 4];
    float4 qa0 = *(const float4*)&g_Q[gbase];
    float4 qa1 = *(const float4*)&g_Q[gbase + 4];

    const int nchunk = SEG_ROWS / 16;   // 32
    for (int ch = 0; ch < nchunk; ++ch) {
        const int s = ch & 1;
        *(float4*)&Ks[s][lrow][lcol]     = ka0;
        *(float4*)&Ks[s][lrow][lcol + 4] = ka1;
        *(float4*)&Qs[s][lrow][lcol]     = qa0;
        *(float4*)&Qs[s][lrow][lcol + 4] = qa1;
        __syncthreads();
        if (ch + 1 < nchunk) {
            size_t gn = gbase + (size_t)(ch + 1) * 16 * DM;
            ka0 = *(const float4*)&g_K[gn];
            ka1 = *(const float4*)&g_K[gn + 4];
            qa0 = *(const float4*)&g_Q[gn];
            qa1 = *(const float4*)&g_Q[gn + 4];
        }
#pragma unroll
        for (int kt = 0; kt < 2; ++kt) {
            unsigned a[4];
            a[0] = __float_as_uint(Ks[s][kt * 8 + tig][wid * 16 + gid]);
            a[1] = __float_as_uint(Ks[s][kt * 8 + tig][wid * 16 + gid + 8]);
            a[2] = __float_as_uint(Ks[s][kt * 8 + tig + 4][wid * 16 + gid]);
            a[3] = __float_as_uint(Ks[s][kt * 8 + tig + 4][wid * 16 + gid + 8]);
#pragma unroll
            for (int nt = 0; nt < 8; ++nt) {
                unsigned b0 = __float_as_uint(Qs[s][kt * 8 + tig][nt * 8 + gid]);
                unsigned b1 = __float_as_uint(Qs[s][kt * 8 + tig + 4][nt * 8 + gid]);
                mma_tf32(acc[nt], a, b0, b1);
            }
        }
        if (tid < 64) {
#pragma unroll
            for (int l = 0; l < 16; ++l) qsv += Qs[s][l][tid];
        }
    }

    float* outp = &g_KtQp[((size_t)seg * BH + bh) * (DEPTH * DEPTH)];
    const int d0 = wid * 16 + gid;
#pragma unroll
    for (int nt = 0; nt < 8; ++nt) {
        const int e = nt * 8 + 2 * tig;
        *(float2*)&outp[d0 * DEPTH + e]       = make_float2(acc[nt][0], acc[nt][1]);
        *(float2*)&outp[(d0 + 8) * DEPTH + e] = make_float2(acc[nt][2], acc[nt][3]);
    }
    if (tid < 64)
        g_qsp[((size_t)seg * BH + bh) * DEPTH + tid] = qsv;
}

// Merged deterministic reduction
__global__ void red_k()
{
    int i = blockIdx.x * 256 + threadIdx.x;
    if (i < BH * DEPTH * DEPTH) {
        float s = 0.0f;
#pragma unroll
        for (int seg = 0; seg < NSEG; ++seg)
            s += g_KtQp[seg * (BH * DEPTH * DEPTH) + i];
        g_KtQ[i] = s;
    } else {
        int j = i - BH * DEPTH * DEPTH;
        if (j < BH * DEPTH) {
            float s = 0.0f;
#pragma unroll
            for (int seg = 0; seg < NSEG; ++seg)
                s += g_qsp[seg * (BH * DEPTH) + j];
            g_qs[j] = s;
        }
    }
}

// ---------------------------------------------------------------------------
// out via mma
// ---------------------------------------------------------------------------
#define OVST 68
#define OSST 66
#define OUT_SMEM ((128 * OVST + 64 * OSST + 64 + 128) * 4)

__global__ __launch_bounds__(128)
void out_k()
{
    extern __shared__ float sm[];
    float* Vs  = sm;
    float* Ss  = sm + 128 * OVST;
    float* qsm = Ss + 64 * OSST;
    float* zs  = qsm + 64;

    const int bh = blockIdx.x;
    const int b = bh >> 4, h = bh & 15;
    const int rowbase = blockIdx.y * 128;
    const int tid = threadIdx.x;
    const int wid = tid >> 5, lane = tid & 31;
    const int gid = lane >> 2, tig = lane & 3;

    {
        const float* src = &g_KtQ[(size_t)bh * (DEPTH * DEPTH)];
#pragma unroll
        for (int i = 0; i < 32; ++i) {
            int idx = tid + i * 128;
            int d = idx >> 6, e = idx & 63;
            Ss[e * OSST + d] = src[idx];
        }
        if (tid < 64) qsm[tid] = g_qs[(size_t)bh * DEPTH + tid];
    }
    {
        const size_t gV = ((size_t)(b * Nn + rowbase)) * DM + h * DEPTH;
#pragma unroll
        for (int i = 0; i < 16; ++i) {
            int idx = tid + i * 128;
            int r = idx >> 4, c4 = (idx & 15) * 4;
            *(float4*)&Vs[r * OVST + c4] = *(const float4*)&g_V[gV + (size_t)r * DM + c4];
        }
    }
    __syncthreads();

    {
        const float q0 = qsm[lane * 2], q1 = qsm[lane * 2 + 1];
        for (int r = 0; r < 32; ++r) {
            const int row = wid * 32 + r;
            float2 kv = *(const float2*)
                &g_K[((size_t)(b * Nn + rowbase + row)) * DM + h * DEPTH + lane * 2];
            float zp = kv.x * q0 + kv.y * q1;
#pragma unroll
            for (int o = 16; o > 0; o >>= 1)
                zp += __shfl_xor_sync(0xFFFFFFFFu, zp, o);
            if (lane == 0) zs[row] = zp;
        }
        __syncwarp();
    }

    float acc[2][8][4];
#pragma unroll
    for (int i = 0; i < 2; ++i)
#pragma unroll
        for (int j = 0; j < 8; ++j)
#pragma unroll
            for (int q = 0; q < 4; ++q) acc[i][j][q] = 0.0f;

#pragma unroll
    for (int kt = 0; kt < 8; ++kt) {
        unsigned a[2][4];
#pragma unroll
        for (int mt = 0; mt < 2; ++mt) {
            const int m0 = wid * 32 + mt * 16;
            a[mt][0] = __float_as_uint(Vs[(m0 + gid) * OVST + kt * 8 + tig]);
            a[mt][1] = __float_as_uint(Vs[(m0 + gid + 8) * OVST + kt * 8 + tig]);
            a[mt][2] = __float_as_uint(Vs[(m0 + gid) * OVST + kt * 8 + tig + 4]);
            a[mt][3] = __float_as_uint(Vs[(m0 + gid + 8) * OVST + kt * 8 + tig + 4]);
        }
#pragma unroll
        for (int nt = 0; nt < 8; ++nt) {
            unsigned b0 = __float_as_uint(Ss[(nt * 8 + gid) * OSST + kt * 8 + tig]);
            unsigned b1 = __float_as_uint(Ss[(nt * 8 + gid) * OSST + kt * 8 + tig + 4]);
            mma_tf32(acc[0][nt], a[0], b0, b1);
            mma_tf32(acc[1][nt], a[1], b0, b1);
        }
    }

#pragma unroll
    for (int mt = 0; mt < 2; ++mt) {
        const int lm = wid * 32 + mt * 16 + gid;
        const float inv0 = 1.0f / (zs[lm] + 1e-9f);
        const float inv1 = 1.0f / (zs[lm + 8] + 1e-9f);
        const size_t grow = ((size_t)(b * Nn + rowbase + lm)) * DM + h * DEPTH;
#pragma unroll
        for (int nt = 0; nt < 8; ++nt) {
            const int cn = nt * 8 + 2 * tig;
            *(float2*)&g_attn[grow + cn] =
                make_float2(acc[mt][nt][0] * inv0, acc[mt][nt][1] * inv0);
            *(float2*)&g_attn[grow + (size_t)8 * DM + cn] =
                make_float2(acc[mt][nt][2] * inv1, acc[mt][nt][3] * inv1);
        }
    }
}

// ---------------------------------------------------------------------------
// ln: residual already folded into g_proj by the O-projection epilogue.
// ---------------------------------------------------------------------------
__global__ __launch_bounds__(256)
void ln_k(const float* __restrict__ gamma, const float* __restrict__ beta,
          float* __restrict__ out)
{
    __shared__ float ws[8];
    const int row = blockIdx.x;
    const int tid = threadIdx.x;
    const int wid = tid >> 5, lane = tid & 31;

    float4 x = *(const float4*)&g_proj[(size_t)row * DM + tid * 4];

    float s = x.x + x.y + x.z + x.w;
#pragma unroll
    for (int o = 16; o > 0; o >>= 1) s += __shfl_xor_sync(0xFFFFFFFFu, s, o);
    if (lane == 0) ws[wid] = s;
    __syncthreads();
    if (tid < 32) {
        float t = (lane < 8) ? ws[lane] : 0.0f;
#pragma unroll
        for (int o = 4; o > 0; o >>= 1) t += __shfl_xor_sync(0xFFFFFFFFu, t, o);
        if (lane == 0) ws[0] = t;
    }
    __syncthreads();
    const float mu = ws[0] * (1.0f / 1024.0f);
    __syncthreads();

    float dx = x.x - mu, dy = x.y - mu, dz = x.z - mu, dw = x.w - mu;
    float v = dx * dx + dy * dy + dz * dz + dw * dw;
#pragma unroll
    for (int o = 16; o > 0; o >>= 1) v += __shfl_xor_sync(0xFFFFFFFFu, v, o);
    if (lane == 0) ws[wid] = v;
    __syncthreads();
    if (tid < 32) {
        float t = (lane < 8) ? ws[lane] : 0.0f;
#pragma unroll
        for (int o = 4; o > 0; o >>= 1) t += __shfl_xor_sync(0xFFFFFFFFu, t, o);
        if (lane == 0) ws[0] = t;
    }
    __syncthreads();
    const float inv = rsqrtf(ws[0] * (1.0f / 1024.0f) + 1e-6f);

    float4 gm = *(const float4*)&gamma[tid * 4];
    float4 bt = *(const float4*)&beta[tid * 4];
    float4 o;
    o.x = dx * inv * gm.x + bt.x;
    o.y = dy * inv * gm.y + bt.y;
    o.z = dz * inv * gm.z + bt.z;
    o.w = dw * inv * gm.w + bt.w;
    *(float4*)&out[(size_t)row * DM + tid * 4] = o;
}

// ---------------------------------------------------------------------------
// Host
// ---------------------------------------------------------------------------
typedef CUresult (*PFN_encodeTiled)(
    CUtensorMap*, CUtensorMapDataType, cuuint32_t, void*,
    const cuuint64_t*, const cuuint64_t*, const cuuint32_t*, const cuuint32_t*,
    CUtensorMapInterleave, CUtensorMapSwizzle, CUtensorMapL2promotion,
    CUtensorMapFloatOOBfill);

static void make_map(PFN_encodeTiled enc, CUtensorMap* m, void* ptr,
                     unsigned long long rows, unsigned box1)
{
    cuuint64_t dims[2]    = {DM, rows};
    cuuint64_t strides[1] = {DM * sizeof(float)};
    cuuint32_t box[2]     = {KC, box1};
    cuuint32_t estr[2]    = {1, 1};
    enc(m, CU_TENSOR_MAP_DATA_TYPE_FLOAT32, 2, ptr, dims, strides, box, estr,
        CU_TENSOR_MAP_INTERLEAVE_NONE, CU_TENSOR_MAP_SWIZZLE_128B,
        CU_TENSOR_MAP_L2_PROMOTION_L2_128B, CU_TENSOR_MAP_FLOAT_OOB_FILL_NONE);
}

extern "C" void kernel_launch(void* const* d_in, const int* in_sizes, int n_in,
                              void* d_out, int out_size)
{
    const float* query = (const float*)d_in[0];
    const float* key_  = (const float*)d_in[1];
    const float* value = (const float*)d_in[2];
    const float* Wq = (const float*)d_in[3];
    const float* bq = (const float*)d_in[4];
    const float* Wk = (const float*)d_in[5];
    const float* bk = (const float*)d_in[6];
    const float* Wv = (const float*)d_in[7];
    const float* bv = (const float*)d_in[8];
    const float* Wo = (const float*)d_in[9];
    const float* bo = (const float*)d_in[10];
    const float* gamma = (const float*)d_in[11];
    const float* beta  = (const float*)d_in[12];
    float* out = (float*)d_out;

    void *pQ, *pK, *pV, *pAttn, *pProj, *pWt;
    cudaGetSymbolAddress(&pQ, g_Q);
    cudaGetSymbolAddress(&pK, g_K);
    cudaGetSymbolAddress(&pV, g_V);
    cudaGetSymbolAddress(&pAttn, g_attn);
    cudaGetSymbolAddress(&pProj, g_proj);
    cudaGetSymbolAddress(&pWt, g_Wt);
    float* Wt = (float*)pWt;

    PFN_encodeTiled enc = nullptr;
    {
        void* fn = nullptr;
        cudaDriverEntryPointQueryResult st;
        cudaGetDriverEntryPoint("cuTensorMapEncodeTiled", &fn,
                                cudaEnableDefault, &st);
        enc = (PFN_encodeTiled)fn;
    }

    CUtensorMap mA[4], mB[4];
    make_map(enc, &mA[0], (void*)query, ROWS, 256);
    make_map(enc, &mA[1], (void*)key_,  ROWS, 256);
    make_map(enc, &mA[2], (void*)value, ROWS, 256);
    make_map(enc, &mA[3], pAttn,        ROWS, 256);
    make_map(enc, &mB[0], Wt + 0 * DM * DM, DM, 128);
    make_map(enc, &mB[1], Wt + 1 * DM * DM, DM, 128);
    make_map(enc, &mB[2], Wt + 2 * DM * DM, DM, 128);
    make_map(enc, &mB[3], Wt + 3 * DM * DM, DM, 128);

    cudaFuncSetAttribute(gemm_qkv_k, cudaFuncAttributeMaxDynamicSharedMemorySize,
                         SM_TOTAL);
    cudaFuncSetAttribute(gemm_o_k, cudaFuncAttributeMaxDynamicSharedMemorySize,
                         SM_TOTAL);
    cudaFuncSetAttribute(out_k, cudaFuncAttributeMaxDynamicSharedMemorySize,
                         OUT_SMEM);

    transpose_k<<<dim3(DM / 32, DM / 32, 4), dim3(32, 8)>>>(Wq, Wk, Wv, Wo, Wt);

    gemm_qkv_k<<<dim3(DM / 128, ROWS / 256, 3), 256, SM_TOTAL>>>(
        mA[0], mA[1], mA[2], mB[0], mB[1], mB[2],
        bq, bk, bv, (float*)pQ, (float*)pK, (float*)pV);

    ktq_k<<<dim3(BH, NSEG), 128>>>();
    red_k<<<(BH * DEPTH * DEPTH + BH * DEPTH + 255) / 256, 256>>>();

    out_k<<<dim3(BH, Nn / 128), 128, OUT_SMEM>>>();

    gemm_o_k<<<dim3(DM / 128, ROWS / 256), 256, SM_TOTAL>>>(
        mA[3], mB[3], bo, (float*)pProj, query);

    ln_k<<<ROWS, 256>>>(gamma, beta, out);
}

// round 17
// speedup vs baseline: 1.0843x; 1.0843x over previous
#include <cuda.h>
#include <cuda_runtime.h>
#include <cuda_bf16.h>
#include <math.h>

// Problem constants
#define Bz 4
#define Nn 4096
#define DM 1024
#define Hh 16
#define DEPTH 64
#define ROWS (Bz * Nn)          // 16384
#define BH (Bz * Hh)            // 64
#define NSEG 8
#define SEG_ROWS (Nn / NSEG)    // 512

// ---------------------------------------------------------------------------
// Scratch (device globals)
// ---------------------------------------------------------------------------
__device__ __align__(128) float g_Q[ROWS * DM];
__device__ __align__(128) float g_K[ROWS * DM];
__device__ __align__(128) float g_V[ROWS * DM];
__device__ __align__(128) float g_attn[ROWS * DM];
__device__ __align__(128) float g_proj[ROWS * DM];
__device__ __align__(128) float g_Wt[4 * DM * DM];
__device__ float g_KtQp[NSEG * BH * DEPTH * DEPTH];
__device__ float g_KtQ[BH * DEPTH * DEPTH];
__device__ float g_qsp[NSEG * BH * DEPTH];
__device__ float g_qs[BH * DEPTH];

__device__ __forceinline__ float tf32r(float x) {
    float r;
    asm("cvt.rna.tf32.f32 %0, %1;" : "=f"(r) : "f"(x));
    return r;
}
__device__ __forceinline__ unsigned smem_u32(const void* p) {
    unsigned a;
    asm("{ .reg .u64 t; cvta.to.shared.u64 t, %1; cvt.u32.u64 %0, t; }"
        : "=r"(a) : "l"(p));
    return a;
}

__device__ __forceinline__ void mma_tf32(float* d, const unsigned* a,
                                         unsigned b0, unsigned b1)
{
    asm volatile(
        "mma.sync.aligned.m16n8k8.row.col.f32.tf32.tf32.f32 "
        "{%0,%1,%2,%3}, {%4,%5,%6,%7}, {%8,%9}, {%0,%1,%2,%3};"
        : "+f"(d[0]), "+f"(d[1]), "+f"(d[2]), "+f"(d[3])
        : "r"(a[0]), "r"(a[1]), "r"(a[2]), "r"(a[3]), "r"(b0), "r"(b1));
}

#define LDMX4(r0, r1, r2, r3, addr) \
    asm volatile("ldmatrix.sync.aligned.m8n8.x4.shared.b16 {%0,%1,%2,%3}, [%4];" \
                 : "=r"(r0), "=r"(r1), "=r"(r2), "=r"(r3) : "r"(addr))

__device__ __forceinline__ void mbar_wait(unsigned mb, unsigned parity) {
    asm volatile(
        "{\n\t.reg .pred P;\n\t"
        "W_%=:\n\t"
        "mbarrier.try_wait.parity.acquire.cta.shared::cta.b64 P, [%0], %1, 0x989680;\n\t"
        "@P bra.uni D_%=;\n\t"
        "bra.uni W_%=;\n\t"
        "D_%=:\n\t}"
        :: "r"(mb), "r"(parity) : "memory");
}
__device__ __forceinline__ void mbar_arrive(unsigned mb) {
    asm volatile("mbarrier.arrive.shared.b64 _, [%0];" :: "r"(mb) : "memory");
}

// ---------------------------------------------------------------------------
// Weight transpose + tf32 rounding
// ---------------------------------------------------------------------------
__global__ void transpose_k(const float* __restrict__ W0, const float* __restrict__ W1,
                            const float* __restrict__ W2, const float* __restrict__ W3,
                            float* __restrict__ Wt)
{
    __shared__ float t[32][33];
    const int m = blockIdx.z;
    const float* W = (m == 0) ? W0 : (m == 1) ? W1 : (m == 2) ? W2 : W3;
    float* dst = Wt + (size_t)m * DM * DM;
    const int bx = blockIdx.x * 32;
    const int by = blockIdx.y * 32;
    const int tx = threadIdx.x, ty = threadIdx.y;
#pragma unroll
    for (int i = 0; i < 32; i += 8)
        t[ty + i][tx] = W[(size_t)(by + ty + i) * DM + bx + tx];
    __syncthreads();
#pragma unroll
    for (int i = 0; i < 32; i += 8)
        dst[(size_t)(bx + ty + i) * DM + by + tx] = tf32r(t[tx][ty + i]);
}

// ---------------------------------------------------------------------------
// tf32 mma.sync GEMM (R15 config): 4 warps (2x2), warp tile 64x64,
// TMA SW128 KC=32, 3 stages, full/empty mbarriers, register fragment
// double-buffering, rotating producer (warp c&3).
// 128 threads, 2 CTAs/SM. act: 0 none, 1 elu+1, 2 residual add.
// ---------------------------------------------------------------------------
#define KC 32
#define NCHUNK (DM / KC)            // 32
#define ASTG 16384
#define SM_MB 0
#define SM_A 1024
#define SM_B (SM_A + 3 * ASTG)
#define SM_TOTAL (SM_B + 3 * ASTG)  // 99328

__device__ __forceinline__ void ld_group(unsigned aB, unsigned bB,
                                         const unsigned* rowA, const unsigned* rowB,
                                         unsigned sw, unsigned* fa, unsigned* fb)
{
#pragma unroll
    for (int mt = 0; mt < 4; ++mt)
        LDMX4(fa[4 * mt], fa[4 * mt + 1], fa[4 * mt + 2], fa[4 * mt + 3],
              aB + rowA[mt] + sw);
#pragma unroll
    for (int p = 0; p < 4; ++p)
        LDMX4(fb[4 * p], fb[4 * p + 1], fb[4 * p + 2], fb[4 * p + 3],
              bB + rowB[p] + sw);
}

__device__ __forceinline__ void gemm_body(
    const CUtensorMap* pA, const CUtensorMap* pB,
    const float* __restrict__ bias, float* __restrict__ C,
    int act, const float* __restrict__ resid)
{
    extern __shared__ char smem[];
    const unsigned sbase = smem_u32(smem);
    const int tid = threadIdx.x;
    const int wid = tid >> 5, lane = tid & 31;
    const int warpM = wid >> 1, warpN = wid & 1;
    const int bm = blockIdx.y * 128;
    const int bn = blockIdx.x * 128;

    if (tid == 0) {
#pragma unroll
        for (int s = 0; s < 3; ++s) {
            asm volatile("mbarrier.init.shared.b64 [%0], 1;"
                         :: "r"(sbase + SM_MB + s * 8) : "memory");      // full
            asm volatile("mbarrier.init.shared.b64 [%0], 4;"
                         :: "r"(sbase + SM_MB + 24 + s * 8) : "memory"); // empty
        }
    }
    __syncthreads();

#define ISSUE_TMA(c)                                                              \
    do {                                                                          \
        const int _s = (c) % 3;                                                   \
        const unsigned _mb = sbase + SM_MB + _s * 8;                              \
        const int _k0 = (c) * KC;                                                 \
        asm volatile("mbarrier.arrive.expect_tx.shared.b64 _, [%0], 32768;"       \
                     :: "r"(_mb) : "memory");                                     \
        asm volatile("cp.async.bulk.tensor.2d.shared::cta.global.tile"            \
                     ".mbarrier::complete_tx::bytes [%0], [%1, {%2, %3}], [%4];"  \
                     :: "r"(sbase + SM_A + _s * ASTG), "l"(pA),                   \
                        "r"(_k0), "r"(bm), "r"(_mb) : "memory");                  \
        asm volatile("cp.async.bulk.tensor.2d.shared::cta.global.tile"            \
                     ".mbarrier::complete_tx::bytes [%0], [%1, {%2, %3}], [%4];"  \
                     :: "r"(sbase + SM_B + _s * ASTG), "l"(pB),                   \
                        "r"(_k0), "r"(bn), "r"(_mb) : "memory");                  \
    } while (0)

    if (tid == 0) { ISSUE_TMA(0); ISSUE_TMA(1); ISSUE_TMA(2); }

    // ldmatrix addressing (SW128 XOR = lr<<4)
    const int lt = lane >> 3, lr = lane & 7;
    const int ldrow = (lt & 1) * 8 + lr;
    unsigned segsw[4];
#pragma unroll
    for (int g = 0; g < 4; ++g)
        segsw[g] = (unsigned)((((lt >> 1) * 16 + g * 32)) ^ (lr << 4));
    unsigned rowA[4], rowB[4];
#pragma unroll
    for (int t4 = 0; t4 < 4; ++t4) {
        rowA[t4] = (warpM * 64 + t4 * 16 + ldrow) * 128;
        rowB[t4] = (warpN * 64 + t4 * 16 + ldrow) * 128;
    }

    float acc[4][8][4];
#pragma unroll
    for (int i = 0; i < 4; ++i)
#pragma unroll
        for (int j = 0; j < 8; ++j)
#pragma unroll
            for (int q = 0; q < 4; ++q) acc[i][j][q] = 0.0f;

    unsigned fA[2][16], fB[2][16];
    int cur = 0;

    // preload chunk 0, group 0
    mbar_wait(sbase + SM_MB + 0, 0);
    ld_group(sbase + SM_A, sbase + SM_B, rowA, rowB, segsw[0], fA[0], fB[0]);

    for (int c = 0; c < NCHUNK; ++c) {
        const int s = c % 3;
        const unsigned aB = sbase + SM_A + s * ASTG;
        const unsigned bB = sbase + SM_B + s * ASTG;
#pragma unroll
        for (int g = 0; g < 4; ++g) {
            const int nxt = cur ^ 1;
            if (g < 3) {
                ld_group(aB, bB, rowA, rowB, segsw[g + 1], fA[nxt], fB[nxt]);
            } else if (c + 1 < NCHUNK) {
                const int ns = (c + 1) % 3;
                mbar_wait(sbase + SM_MB + ns * 8, ((c + 1) / 3) & 1);
                ld_group(sbase + SM_A + ns * ASTG, sbase + SM_B + ns * ASTG,
                         rowA, rowB, segsw[0], fA[nxt], fB[nxt]);
            }
            const unsigned* af = fA[cur];
            const unsigned* bf = fB[cur];
#pragma unroll
            for (int mt = 0; mt < 4; ++mt)
#pragma unroll
                for (int p = 0; p < 4; ++p) {
                    mma_tf32(acc[mt][2 * p],     af + 4 * mt, bf[4 * p], bf[4 * p + 2]);
                    mma_tf32(acc[mt][2 * p + 1], af + 4 * mt, bf[4 * p + 1], bf[4 * p + 3]);
                }
            cur = nxt;
        }
        // all stage-c LDSMs complete (their consumer MMAs issued above)
        if (lane == 0) mbar_arrive(sbase + SM_MB + 24 + s * 8);
        // rotating producer: warp (c&3) refills stage s with chunk c+3
        if (c + 3 < NCHUNK && wid == (c & 3) && lane == 0) {
            mbar_wait(sbase + SM_MB + 24 + s * 8, (c / 3) & 1);
            ISSUE_TMA(c + 3);
        }
    }

    // epilogue (per-warp accumulators; no sync needed)
    const int gid = lane >> 2, tig = lane & 3;
#pragma unroll
    for (int mt = 0; mt < 4; ++mt) {
        const int r = bm + warpM * 64 + mt * 16 + gid;
#pragma unroll
        for (int nt = 0; nt < 8; ++nt) {
            const int cn = bn + warpN * 64 + nt * 8 + 2 * tig;
            const float b0 = bias[cn], b1 = bias[cn + 1];
            float v0 = acc[mt][nt][0] + b0;
            float v1 = acc[mt][nt][1] + b1;
            float v2 = acc[mt][nt][2] + b0;
            float v3 = acc[mt][nt][3] + b1;
            if (act == 1) {
                v0 = (v0 > 0.0f) ? (v0 + 1.0f) : __expf(v0);
                v1 = (v1 > 0.0f) ? (v1 + 1.0f) : __expf(v1);
                v2 = (v2 > 0.0f) ? (v2 + 1.0f) : __expf(v2);
                v3 = (v3 > 0.0f) ? (v3 + 1.0f) : __expf(v3);
            } else if (act == 2) {
                float2 r0 = *(const float2*)&resid[(size_t)r * DM + cn];
                float2 r1 = *(const float2*)&resid[(size_t)(r + 8) * DM + cn];
                v0 += r0.x; v1 += r0.y; v2 += r1.x; v3 += r1.y;
            }
            *(float2*)&C[(size_t)r * DM + cn] = make_float2(v0, v1);
            *(float2*)&C[(size_t)(r + 8) * DM + cn] = make_float2(v2, v3);
        }
    }
#undef ISSUE_TMA
}

__global__ __launch_bounds__(128, 2)
void gemm_qkv_k(const __grid_constant__ CUtensorMap tA0,
                const __grid_constant__ CUtensorMap tA1,
                const __grid_constant__ CUtensorMap tA2,
                const __grid_constant__ CUtensorMap tB0,
                const __grid_constant__ CUtensorMap tB1,
                const __grid_constant__ CUtensorMap tB2,
                const float* __restrict__ b0, const float* __restrict__ b1,
                const float* __restrict__ b2,
                float* __restrict__ C0, float* __restrict__ C1,
                float* __restrict__ C2)
{
    const int z = blockIdx.z;
    const CUtensorMap* pA = (z == 0) ? &tA0 : (z == 1) ? &tA1 : &tA2;
    const CUtensorMap* pB = (z == 0) ? &tB0 : (z == 1) ? &tB1 : &tB2;
    const float* bias = (z == 0) ? b0 : (z == 1) ? b1 : b2;
    float* C = (z == 0) ? C0 : (z == 1) ? C1 : C2;
    gemm_body(pA, pB, bias, C, (z < 2) ? 1 : 0, (const float*)0);
}

__global__ __launch_bounds__(128, 2)
void gemm_o_k(const __grid_constant__ CUtensorMap tA,
              const __grid_constant__ CUtensorMap tB,
              const float* __restrict__ bias, float* __restrict__ C,
              const float* __restrict__ resid)
{
    gemm_body(&tA, &tB, bias, C, 2, resid);
}

// ---------------------------------------------------------------------------
// ktq via mma (NSEG=8: 32 chunks of 16 rows)
// ---------------------------------------------------------------------------
__global__ __launch_bounds__(128)
void ktq_k()
{
    __shared__ float Ks[2][16][68];
    __shared__ float Qs[2][16][68];

    const int bh = blockIdx.x;
    const int b = bh >> 4, h = bh & 15;
    const int seg = blockIdx.y;
    const int tid = threadIdx.x;
    const int wid = tid >> 5, lane = tid & 31;
    const int gid = lane >> 2, tig = lane & 3;
    const int lrow = tid >> 3;
    const int lcol = (tid & 7) * 8;

    float acc[8][4];
#pragma unroll
    for (int j = 0; j < 8; ++j)
#pragma unroll
        for (int q = 0; q < 4; ++q) acc[j][q] = 0.0f;
    float qsv = 0.0f;

    size_t gbase = ((size_t)(b * Nn + seg * SEG_ROWS + lrow)) * DM + h * DEPTH + lcol;
    float4 ka0 = *(const float4*)&g_K[gbase];
    float4 ka1 = *(const float4*)&g_K[gbase + 4];
    float4 qa0 = *(const float4*)&g_Q[gbase];
    float4 qa1 = *(const float4*)&g_Q[gbase + 4];

    const int nchunk = SEG_ROWS / 16;   // 32
    for (int ch = 0; ch < nchunk; ++ch) {
        const int s = ch & 1;
        *(float4*)&Ks[s][lrow][lcol]     = ka0;
        *(float4*)&Ks[s][lrow][lcol + 4] = ka1;
        *(float4*)&Qs[s][lrow][lcol]     = qa0;
        *(float4*)&Qs[s][lrow][lcol + 4] = qa1;
        __syncthreads();
        if (ch + 1 < nchunk) {
            size_t gn = gbase + (size_t)(ch + 1) * 16 * DM;
            ka0 = *(const float4*)&g_K[gn];
            ka1 = *(const float4*)&g_K[gn + 4];
            qa0 = *(const float4*)&g_Q[gn];
            qa1 = *(const float4*)&g_Q[gn + 4];
        }
#pragma unroll
        for (int kt = 0; kt < 2; ++kt) {
            unsigned a[4];
            a[0] = __float_as_uint(Ks[s][kt * 8 + tig][wid * 16 + gid]);
            a[1] = __float_as_uint(Ks[s][kt * 8 + tig][wid * 16 + gid + 8]);
            a[2] = __float_as_uint(Ks[s][kt * 8 + tig + 4][wid * 16 + gid]);
            a[3] = __float_as_uint(Ks[s][kt * 8 + tig + 4][wid * 16 + gid + 8]);
#pragma unroll
            for (int nt = 0; nt < 8; ++nt) {
                unsigned b0 = __float_as_uint(Qs[s][kt * 8 + tig][nt * 8 + gid]);
                unsigned b1 = __float_as_uint(Qs[s][kt * 8 + tig + 4][nt * 8 + gid]);
                mma_tf32(acc[nt], a, b0, b1);
            }
        }
        if (tid < 64) {
#pragma unroll
            for (int l = 0; l < 16; ++l) qsv += Qs[s][l][tid];
        }
    }

    float* outp = &g_KtQp[((size_t)seg * BH + bh) * (DEPTH * DEPTH)];
    const int d0 = wid * 16 + gid;
#pragma unroll
    for (int nt = 0; nt < 8; ++nt) {
        const int e = nt * 8 + 2 * tig;
        *(float2*)&outp[d0 * DEPTH + e]       = make_float2(acc[nt][0], acc[nt][1]);
        *(float2*)&outp[(d0 + 8) * DEPTH + e] = make_float2(acc[nt][2], acc[nt][3]);
    }
    if (tid < 64)
        g_qsp[((size_t)seg * BH + bh) * DEPTH + tid] = qsv;
}

// Merged deterministic reduction
__global__ void red_k()
{
    int i = blockIdx.x * 256 + threadIdx.x;
    if (i < BH * DEPTH * DEPTH) {
        float s = 0.0f;
#pragma unroll
        for (int seg = 0; seg < NSEG; ++seg)
            s += g_KtQp[seg * (BH * DEPTH * DEPTH) + i];
        g_KtQ[i] = s;
    } else {
        int j = i - BH * DEPTH * DEPTH;
        if (j < BH * DEPTH) {
            float s = 0.0f;
#pragma unroll
            for (int seg = 0; seg < NSEG; ++seg)
                s += g_qsp[seg * (BH * DEPTH) + j];
            g_qs[j] = s;
        }
    }
}

// ---------------------------------------------------------------------------
// out via mma
// ---------------------------------------------------------------------------
#define OVST 68
#define OSST 66
#define OUT_SMEM ((128 * OVST + 64 * OSST + 64 + 128) * 4)

__global__ __launch_bounds__(128)
void out_k()
{
    extern __shared__ float sm[];
    float* Vs  = sm;
    float* Ss  = sm + 128 * OVST;
    float* qsm = Ss + 64 * OSST;
    float* zs  = qsm + 64;

    const int bh = blockIdx.x;
    const int b = bh >> 4, h = bh & 15;
    const int rowbase = blockIdx.y * 128;
    const int tid = threadIdx.x;
    const int wid = tid >> 5, lane = tid & 31;
    const int gid = lane >> 2, tig = lane & 3;

    {
        const float* src = &g_KtQ[(size_t)bh * (DEPTH * DEPTH)];
#pragma unroll
        for (int i = 0; i < 32; ++i) {
            int idx = tid + i * 128;
            int d = idx >> 6, e = idx & 63;
            Ss[e * OSST + d] = src[idx];
        }
        if (tid < 64) qsm[tid] = g_qs[(size_t)bh * DEPTH + tid];
    }
    {
        const size_t gV = ((size_t)(b * Nn + rowbase)) * DM + h * DEPTH;
#pragma unroll
        for (int i = 0; i < 16; ++i) {
            int idx = tid + i * 128;
            int r = idx >> 4, c4 = (idx & 15) * 4;
            *(float4*)&Vs[r * OVST + c4] = *(const float4*)&g_V[gV + (size_t)r * DM + c4];
        }
    }
    __syncthreads();

    {
        const float q0 = qsm[lane * 2], q1 = qsm[lane * 2 + 1];
        for (int r = 0; r < 32; ++r) {
            const int row = wid * 32 + r;
            float2 kv = *(const float2*)
                &g_K[((size_t)(b * Nn + rowbase + row)) * DM + h * DEPTH + lane * 2];
            float zp = kv.x * q0 + kv.y * q1;
#pragma unroll
            for (int o = 16; o > 0; o >>= 1)
                zp += __shfl_xor_sync(0xFFFFFFFFu, zp, o);
            if (lane == 0) zs[row] = zp;
        }
        __syncwarp();
    }

    float acc[2][8][4];
#pragma unroll
    for (int i = 0; i < 2; ++i)
#pragma unroll
        for (int j = 0; j < 8; ++j)
#pragma unroll
            for (int q = 0; q < 4; ++q) acc[i][j][q] = 0.0f;

#pragma unroll
    for (int kt = 0; kt < 8; ++kt) {
        unsigned a[2][4];
#pragma unroll
        for (int mt = 0; mt < 2; ++mt) {
            const int m0 = wid * 32 + mt * 16;
            a[mt][0] = __float_as_uint(Vs[(m0 + gid) * OVST + kt * 8 + tig]);
            a[mt][1] = __float_as_uint(Vs[(m0 + gid + 8) * OVST + kt * 8 + tig]);
            a[mt][2] = __float_as_uint(Vs[(m0 + gid) * OVST + kt * 8 + tig + 4]);
            a[mt][3] = __float_as_uint(Vs[(m0 + gid + 8) * OVST + kt * 8 + tig + 4]);
        }
#pragma unroll
        for (int nt = 0; nt < 8; ++nt) {
            unsigned b0 = __float_as_uint(Ss[(nt * 8 + gid) * OSST + kt * 8 + tig]);
            unsigned b1 = __float_as_uint(Ss[(nt * 8 + gid) * OSST + kt * 8 + tig + 4]);
            mma_tf32(acc[0][nt], a[0], b0, b1);
            mma_tf32(acc[1][nt], a[1], b0, b1);
        }
    }

#pragma unroll
    for (int mt = 0; mt < 2; ++mt) {
        const int lm = wid * 32 + mt * 16 + gid;
        const float inv0 = 1.0f / (zs[lm] + 1e-9f);
        const float inv1 = 1.0f / (zs[lm + 8] + 1e-9f);
        const size_t grow = ((size_t)(b * Nn + rowbase + lm)) * DM + h * DEPTH;
#pragma unroll
        for (int nt = 0; nt < 8; ++nt) {
            const int cn = nt * 8 + 2 * tig;
            *(float2*)&g_attn[grow + cn] =
                make_float2(acc[mt][nt][0] * inv0, acc[mt][nt][1] * inv0);
            *(float2*)&g_attn[grow + (size_t)8 * DM + cn] =
                make_float2(acc[mt][nt][2] * inv1, acc[mt][nt][3] * inv1);
        }
    }
}

// ---------------------------------------------------------------------------
// ln: residual already folded into g_proj by the O-projection epilogue.
// ---------------------------------------------------------------------------
__global__ __launch_bounds__(256)
void ln_k(const float* __restrict__ gamma, const float* __restrict__ beta,
          float* __restrict__ out)
{
    __shared__ float ws[8];
    const int row = blockIdx.x;
    const int tid = threadIdx.x;
    const int wid = tid >> 5, lane = tid & 31;

    float4 x = *(const float4*)&g_proj[(size_t)row * DM + tid * 4];

    float s = x.x + x.y + x.z + x.w;
#pragma unroll
    for (int o = 16; o > 0; o >>= 1) s += __shfl_xor_sync(0xFFFFFFFFu, s, o);
    if (lane == 0) ws[wid] = s;
    __syncthreads();
    if (tid < 32) {
        float t = (lane < 8) ? ws[lane] : 0.0f;
#pragma unroll
        for (int o = 4; o > 0; o >>= 1) t += __shfl_xor_sync(0xFFFFFFFFu, t, o);
        if (lane == 0) ws[0] = t;
    }
    __syncthreads();
    const float mu = ws[0] * (1.0f / 1024.0f);
    __syncthreads();

    float dx = x.x - mu, dy = x.y - mu, dz = x.z - mu, dw = x.w - mu;
    float v = dx * dx + dy * dy + dz * dz + dw * dw;
#pragma unroll
    for (int o = 16; o > 0; o >>= 1) v += __shfl_xor_sync(0xFFFFFFFFu, v, o);
    if (lane == 0) ws[wid] = v;
    __syncthreads();
    if (tid < 32) {
        float t = (lane < 8) ? ws[lane] : 0.0f;
#pragma unroll
        for (int o = 4; o > 0; o >>= 1) t += __shfl_xor_sync(0xFFFFFFFFu, t, o);
        if (lane == 0) ws[0] = t;
    }
    __syncthreads();
    const float inv = rsqrtf(ws[0] * (1.0f / 1024.0f) + 1e-6f);

    float4 gm = *(const float4*)&gamma[tid * 4];
    float4 bt = *(const float4*)&beta[tid * 4];
    float4 o;
    o.x = dx * inv * gm.x + bt.x;
    o.y = dy * inv * gm.y + bt.y;
    o.z = dz * inv * gm.z + bt.z;
    o.w = dw * inv * gm.w + bt.w;
    *(float4*)&out[(size_t)row * DM + tid * 4] = o;
}

// ---------------------------------------------------------------------------
// Host
// ---------------------------------------------------------------------------
typedef CUresult (*PFN_encodeTiled)(
    CUtensorMap*, CUtensorMapDataType, cuuint32_t, void*,
    const cuuint64_t*, const cuuint64_t*, const cuuint32_t*, const cuuint32_t*,
    CUtensorMapInterleave, CUtensorMapSwizzle, CUtensorMapL2promotion,
    CUtensorMapFloatOOBfill);

static void make_map(PFN_encodeTiled enc, CUtensorMap* m, void* ptr,
                     unsigned long long rows)
{
    cuuint64_t dims[2]    = {DM, rows};
    cuuint64_t strides[1] = {DM * sizeof(float)};
    cuuint32_t box[2]     = {KC, 128};
    cuuint32_t estr[2]    = {1, 1};
    enc(m, CU_TENSOR_MAP_DATA_TYPE_FLOAT32, 2, ptr, dims, strides, box, estr,
        CU_TENSOR_MAP_INTERLEAVE_NONE, CU_TENSOR_MAP_SWIZZLE_128B,
        CU_TENSOR_MAP_L2_PROMOTION_L2_128B, CU_TENSOR_MAP_FLOAT_OOB_FILL_NONE);
}

extern "C" void kernel_launch(void* const* d_in, const int* in_sizes, int n_in,
                              void* d_out, int out_size)
{
    const float* query = (const float*)d_in[0];
    const float* key_  = (const float*)d_in[1];
    const float* value = (const float*)d_in[2];
    const float* Wq = (const float*)d_in[3];
    const float* bq = (const float*)d_in[4];
    const float* Wk = (const float*)d_in[5];
    const float* bk = (const float*)d_in[6];
    const float* Wv = (const float*)d_in[7];
    const float* bv = (const float*)d_in[8];
    const float* Wo = (const float*)d_in[9];
    const float* bo = (const float*)d_in[10];
    const float* gamma = (const float*)d_in[11];
    const float* beta  = (const float*)d_in[12];
    float* out = (float*)d_out;

    void *pQ, *pK, *pV, *pAttn, *pProj, *pWt;
    cudaGetSymbolAddress(&pQ, g_Q);
    cudaGetSymbolAddress(&pK, g_K);
    cudaGetSymbolAddress(&pV, g_V);
    cudaGetSymbolAddress(&pAttn, g_attn);
    cudaGetSymbolAddress(&pProj, g_proj);
    cudaGetSymbolAddress(&pWt, g_Wt);
    float* Wt = (float*)pWt;

    PFN_encodeTiled enc = nullptr;
    {
        void* fn = nullptr;
        cudaDriverEntryPointQueryResult st;
        cudaGetDriverEntryPoint("cuTensorMapEncodeTiled", &fn,
                                cudaEnableDefault, &st);
        enc = (PFN_encodeTiled)fn;
    }

    CUtensorMap mA[4], mB[4];
    make_map(enc, &mA[0], (void*)query, ROWS);
    make_map(enc, &mA[1], (void*)key_,  ROWS);
    make_map(enc, &mA[2], (void*)value, ROWS);
    make_map(enc, &mA[3], pAttn,        ROWS);
    make_map(enc, &mB[0], Wt + 0 * DM * DM, DM);
    make_map(enc, &mB[1], Wt + 1 * DM * DM, DM);
    make_map(enc, &mB[2], Wt + 2 * DM * DM, DM);
    make_map(enc, &mB[3], Wt + 3 * DM * DM, DM);

    cudaFuncSetAttribute(gemm_qkv_k, cudaFuncAttributeMaxDynamicSharedMemorySize,
                         SM_TOTAL);
    cudaFuncSetAttribute(gemm_o_k, cudaFuncAttributeMaxDynamicSharedMemorySize,
                         SM_TOTAL);
    cudaFuncSetAttribute(out_k, cudaFuncAttributeMaxDynamicSharedMemorySize,
                         OUT_SMEM);

    transpose_k<<<dim3(DM / 32, DM / 32, 4), dim3(32, 8)>>>(Wq, Wk, Wv, Wo, Wt);

    gemm_qkv_k<<<dim3(DM / 128, ROWS / 128, 3), 128, SM_TOTAL>>>(
        mA[0], mA[1], mA[2], mB[0], mB[1], mB[2],
        bq, bk, bv, (float*)pQ, (float*)pK, (float*)pV);

    ktq_k<<<dim3(BH, NSEG), 128>>>();
    red_k<<<(BH * DEPTH * DEPTH + BH * DEPTH + 255) / 256, 256>>>();

    out_k<<<dim3(BH, Nn / 128), 128, OUT_SMEM>>>();

    gemm_o_k<<<dim3(DM / 128, ROWS / 128), 128, SM_TOTAL>>>(
        mA[3], mB[3], bo, (float*)pProj, query);

    ln_k<<<ROWS, 256>>>(gamma, beta, out);
}